// round 10
// baseline (speedup 1.0000x reference)
#include <cuda_runtime.h>
#include <math.h>

#define NN 50000
#define EE 500000
#define CLAMPV 5.0f

// ---------------- scratch ----------------------------------------------------
__device__ float g_Qh[NN * 128];
__device__ float g_Kh[NN * 128];
__device__ float g_Vh[NN * 128];
__device__ float g_eexp[(size_t)EE * 8];
__device__ float g_denom[NN * 8];
__device__ float g_rowV[NN * 128];

// ---------------- helpers ----------------------------------------------------
__device__ __forceinline__ void red_add_v4(float* addr, float a, float b, float c, float d) {
    asm volatile("red.global.add.v4.f32 [%0], {%1,%2,%3,%4};"
                 :: "l"(addr), "f"(a), "f"(b), "f"(c), "f"(d) : "memory");
}
// packed 2-lane fp32 fma: d = a*b + d  (per-lane IEEE fp32)
__device__ __forceinline__ void fma2(unsigned long long& d,
                                     unsigned long long a, unsigned long long b) {
    asm("fma.rn.f32x2 %0, %1, %2, %0;" : "+l"(d) : "l"(a), "l"(b));
}
__device__ __forceinline__ unsigned long long pack2(float x) {
    unsigned long long r;
    asm("mov.b64 %0, {%1, %1};" : "=l"(r) : "f"(x));
    return r;
}
__device__ __forceinline__ void unpack2(unsigned long long v, float& lo, float& hi) {
    asm("mov.b64 {%0, %1}, %2;" : "=f"(lo), "=f"(hi) : "l"(v));
}

// ---------------- zero scratch ------------------------------------------------
__global__ void zero_kernel() {
    int stride = gridDim.x * blockDim.x;
    int total = NN * 128 + NN * 8;
    for (int i = blockIdx.x * blockDim.x + threadIdx.x; i < total; i += stride) {
        if (i < NN * 128) g_rowV[i] = 0.f;
        else              g_denom[i - NN * 128] = 0.f;
    }
}

// ---------------- node GEMM (fp32, proven round 1) -----------------------------
__global__ __launch_bounds__(256) void node_gemm(
    const float* __restrict__ x,
    const float* __restrict__ WQ, const float* __restrict__ bQ,
    const float* __restrict__ WK, const float* __restrict__ bK,
    const float* __restrict__ WV, const float* __restrict__ bV,
    float* __restrict__ d_out)
{
    const int which = blockIdx.y;
    const float* W    = (which == 0) ? WQ : (which == 1) ? WK : WV;
    const float* bias = (which == 0) ? bQ : (which == 1) ? bK : bV;
    float* out        = (which == 0) ? g_Qh : (which == 1) ? g_Kh : g_Vh;

    __shared__ float As[64 * 16];
    __shared__ float Bs[16 * 128];

    const int tid = threadIdx.x;
    const int tx = tid & 15, ty = tid >> 4;
    const int m0 = blockIdx.x * 64;

    const int ar = tid >> 2;
    const int ac = (tid & 3) * 4;
    const int brow = tid >> 4;
    const int bcol = (tid & 15) * 8;

    float acc[4][8];
    #pragma unroll
    for (int i = 0; i < 4; i++)
        #pragma unroll
        for (int j = 0; j < 8; j++) acc[i][j] = 0.f;

    for (int k0 = 0; k0 < 128; k0 += 16) {
        float4 av = make_float4(0.f, 0.f, 0.f, 0.f);
        int m = m0 + ar;
        if (m < NN) av = *(const float4*)&x[(size_t)m * 128 + k0 + ac];
        *(float4*)&As[ar * 16 + ac] = av;
        *(float4*)&Bs[brow * 128 + bcol]     = *(const float4*)&W[(size_t)(k0 + brow) * 128 + bcol];
        *(float4*)&Bs[brow * 128 + bcol + 4] = *(const float4*)&W[(size_t)(k0 + brow) * 128 + bcol + 4];
        __syncthreads();
        #pragma unroll
        for (int k = 0; k < 16; k++) {
            float a[4], b[8];
            #pragma unroll
            for (int i = 0; i < 4; i++) a[i] = As[(ty * 4 + i) * 16 + k];
            #pragma unroll
            for (int j = 0; j < 8; j++) b[j] = Bs[k * 128 + tx * 8 + j];
            #pragma unroll
            for (int i = 0; i < 4; i++)
                #pragma unroll
                for (int j = 0; j < 8; j++)
                    acc[i][j] = fmaf(a[i], b[j], acc[i][j]);
        }
        __syncthreads();
    }

    #pragma unroll
    for (int i = 0; i < 4; i++) {
        int m = m0 + ty * 4 + i;
        if (m >= NN) continue;
        #pragma unroll
        for (int j = 0; j < 8; j++) {
            int c = tx * 8 + j;
            float v = acc[i][j] + bias[c];
            out[(size_t)m * 128 + c] = v;
            if (which == 0) d_out[(size_t)m * 128 + c] = v;
        }
    }
}

// ---------------- edge GEMM fp32x2: 64(M) x 256(N), 8x8 microtile -------------
// Inner loop on packed fma.rn.f32x2 (2 fp32 FMA / instr). Thread owns cols
// {tx*4..tx*4+3} and {128+tx*4..+3}; B LDS.128 is phase-contiguous (no
// bank conflicts). One CTA covers all 8 heads; ea read exactly once.
__global__ __launch_bounds__(256) void edge_gemm_f32(
    const float* __restrict__ ea,
    const float* __restrict__ WE, const float* __restrict__ bE,
    const int* __restrict__ edge_index,
    const float* __restrict__ Aw,
    float* __restrict__ d_out)
{
    extern __shared__ float sm[];
    float* As  = sm;            // [64][16]
    float* Bs  = sm + 1024;     // [16][256]
    float* Ex  = sm;            // [64][256] (aliases As/Bs after compute)
    float* AwS = sm + 16384;    // [128]

    const int tid = threadIdx.x;
    const int tx = tid & 31, ty = tid >> 5;   // 32 x 8 thread grid
    const int m0 = blockIdx.x * 64;

    if (tid < 128) AwS[tid] = Aw[tid];

    const int ar = tid >> 2;            // 0..63
    const int ac = (tid & 3) * 4;       // 0,4,8,12
    const int brow = tid >> 4;          // 0..15
    const int bcol = (tid & 15) * 16;   // 0..240

    // acc[i][jp]: jp0->cols cL+0,1  jp1->cL+2,3  jp2->cH+0,1  jp3->cH+2,3
    unsigned long long acc[8][4];
    #pragma unroll
    for (int i = 0; i < 8; i++)
        #pragma unroll
        for (int jp = 0; jp < 4; jp++) acc[i][jp] = 0ull;

    const int cL = tx * 4;
    const int cH = 128 + tx * 4;

    for (int k0 = 0; k0 < 128; k0 += 16) {
        __syncthreads();   // previous compute done before overwriting smem
        float4 av = make_float4(0.f, 0.f, 0.f, 0.f);
        int m = m0 + ar;
        if (m < EE) av = *(const float4*)&ea[(size_t)m * 128 + k0 + ac];
        *(float4*)&As[ar * 16 + ac] = av;
        const float* wrow = &WE[(size_t)(k0 + brow) * 256 + bcol];
        #pragma unroll
        for (int q = 0; q < 4; q++)
            *(float4*)&Bs[brow * 256 + bcol + q * 4] = *(const float4*)&wrow[q * 4];
        __syncthreads();

        #pragma unroll
        for (int k = 0; k < 16; k++) {
            unsigned long long aa[8];
            #pragma unroll
            for (int i = 0; i < 8; i++)
                aa[i] = pack2(As[(ty * 8 + i) * 16 + k]);   // broadcast load + pack
            // two phase-contiguous LDS.128: each float4 = 2 x f32x2 pairs
            float4 bL = *(const float4*)&Bs[k * 256 + cL];
            float4 bH = *(const float4*)&Bs[k * 256 + cH];
            unsigned long long b2[4];
            b2[0] = ((const unsigned long long*)&bL)[0];
            b2[1] = ((const unsigned long long*)&bL)[1];
            b2[2] = ((const unsigned long long*)&bH)[0];
            b2[3] = ((const unsigned long long*)&bH)[1];
            #pragma unroll
            for (int i = 0; i < 8; i++) {
                fma2(acc[i][0], aa[i], b2[0]);
                fma2(acc[i][1], aa[i], b2[1]);
                fma2(acc[i][2], aa[i], b2[2]);
                fma2(acc[i][3], aa[i], b2[3]);
            }
        }
    }
    __syncthreads();

    // ---- stash Ex (+bias) ----
    #pragma unroll
    for (int i = 0; i < 8; i++) {
        int r = ty * 8 + i;
        #pragma unroll
        for (int jp = 0; jp < 4; jp++) {
            int c = (jp < 2) ? (cL + jp * 2) : (cH + (jp - 2) * 2);
            float lo, hi;
            unpack2(acc[i][jp], lo, hi);
            Ex[r * 256 + c]     = lo + bE[c];
            Ex[r * 256 + c + 1] = hi + bE[c + 1];
        }
    }
    __syncthreads();

    float* connOut = d_out + (size_t)NN * 128;

    // ---- conn: 64 edges * 8 heads * 16 dims = 8192 values, 32 per thread ----
    for (int idx = tid; idx < 64 * 128; idx += 256) {
        int el  = idx >> 7;
        int rem = idx & 127;
        int gg  = rem >> 4;     // head 0..7
        int d   = rem & 15;
        int e   = m0 + el;
        float x1 = Ex[el * 256 + gg * 32 + d];
        float x2 = Ex[el * 256 + gg * 32 + 16 + d];
        float s2 = x1 * x2;
        float sc2 = copysignf(sqrtf(fabsf(s2)), s2);
        if (e < EE) {
            int src = edge_index[e];
            int dst = edge_index[EE + e];
            float conn = g_Kh[(size_t)src * 128 + gg * 16 + d]
                       + g_Qh[(size_t)dst * 128 + gg * 16 + d] + sc2;
            connOut[(size_t)e * 128 + gg * 16 + d] = conn;
            Ex[el * 256 + gg * 32 + d] = conn;
        }
    }
    __syncthreads();

    // ---- score per (edge, head): 512 tasks, 2 per thread ----
    #pragma unroll
    for (int it = 0; it < 2; it++) {
        int t  = tid + it * 256;
        int el = t >> 3;
        int gg = t & 7;
        int e  = m0 + el;
        if (e < EE) {
            float s = 0.f;
            #pragma unroll
            for (int d = 0; d < 16; d++)
                s = fmaf(Ex[el * 256 + gg * 32 + d], AwS[d * 8 + gg], s);
            s = fminf(fmaxf(s, -CLAMPV), CLAMPV);
            float eev = expf(s);
            g_eexp[(size_t)e * 8 + gg] = eev;
            int dst = edge_index[EE + e];
            atomicAdd(&g_denom[dst * 8 + gg], eev);
        }
    }
}

// ---------------- aggregation: warp per edge (proven) -------------------------
__global__ __launch_bounds__(256) void aggregate(
    const int* __restrict__ edge_index,
    float* __restrict__ d_out)
{
    const int warp = threadIdx.x >> 5;
    const int lane = threadIdx.x & 31;
    const size_t e = (size_t)blockIdx.x * 8 + warp;
    if (e >= EE) return;

    const int src = edge_index[e];
    const int dst = edge_index[EE + e];
    const int h = lane >> 2;

    float den  = g_denom[dst * 8 + h];
    float attn = g_eexp[e * 8 + h] / (den + 1e-16f);

    const float4* Vh4   = (const float4*)g_Vh;
    const float4* conn4 = (const float4*)(d_out + (size_t)NN * 128);
    float4 v = Vh4[(size_t)src * 32 + lane];
    float4 c = conn4[e * 32 + lane];

    float4* out4 = (float4*)d_out;
    float4* row4 = (float4*)g_rowV;
    red_add_v4((float*)&out4[(size_t)dst * 32 + lane], v.x * attn, v.y * attn, v.z * attn, v.w * attn);
    red_add_v4((float*)&row4[(size_t)dst * 32 + lane], c.x * attn, c.y * attn, c.z * attn, c.w * attn);
}

// ---------------- finalize: Vo += rowV @ VeRow per head (proven) --------------
__global__ __launch_bounds__(128) void finalize(
    const float* __restrict__ VeRow,
    float* __restrict__ d_out)
{
    __shared__ float Vs[2048];
    const int tid = threadIdx.x;
    for (int i = tid; i < 2048; i += 128) Vs[i] = VeRow[i];
    __syncthreads();

    const int h = tid >> 4, c = tid & 15;
    const int n0 = blockIdx.x * 32;
    const int nend = (n0 + 32 < NN) ? n0 + 32 : NN;
    for (int n = n0; n < nend; n++) {
        float acc = 0.f;
        #pragma unroll
        for (int d = 0; d < 16; d++)
            acc = fmaf(g_rowV[(size_t)n * 128 + h * 16 + d], Vs[d * 128 + h * 16 + c], acc);
        d_out[(size_t)n * 128 + h * 16 + c] += acc;
    }
}

// ---------------- launch ------------------------------------------------------
#define EDGE_SM ((64 * 256 + 128) * 4)   // Ex + AwS = 66048 bytes

extern "C" void kernel_launch(void* const* d_in, const int* in_sizes, int n_in,
                              void* d_out, int out_size)
{
    const float* x    = (const float*)d_in[0];
    const float* ea   = (const float*)d_in[1];
    const int*   eidx = (const int*)  d_in[2];
    const float* WQ   = (const float*)d_in[3];
    const float* bQ   = (const float*)d_in[4];
    const float* WK   = (const float*)d_in[5];
    const float* bK   = (const float*)d_in[6];
    const float* WE   = (const float*)d_in[7];
    const float* bE   = (const float*)d_in[8];
    const float* WV   = (const float*)d_in[9];
    const float* bV   = (const float*)d_in[10];
    const float* Aw   = (const float*)d_in[11];
    const float* VeRow= (const float*)d_in[12];
    float* out = (float*)d_out;

    static bool attr_set = false;
    if (!attr_set) {
        cudaFuncSetAttribute(edge_gemm_f32,
                             cudaFuncAttributeMaxDynamicSharedMemorySize, EDGE_SM);
        attr_set = true;
    }

    zero_kernel<<<1024, 256>>>();

    dim3 gn((NN + 63) / 64, 3);
    node_gemm<<<gn, 256>>>(x, WQ, bQ, WK, bK, WV, bV, out);

    edge_gemm_f32<<<(EE + 63) / 64, 256, EDGE_SM>>>(ea, WE, bE, eidx, Aw, out);

    aggregate<<<(EE + 7) / 8, 256>>>(eidx, out);

    finalize<<<(NN + 31) / 32, 128>>>(VeRow, out);
}